// round 14
// baseline (speedup 1.0000x reference)
#include <cuda_runtime.h>
#include <cuda_fp16.h>
#include <math.h>
#include <stdint.h>

#define BB  128   // batch
#define TT  512   // time
#define II  300   // input dim
#define HH  150   // hidden per dir
#define G3  450   // 3*H
#define KK  6     // topics
#define CC  300   // attn context dim
#define THD 20    // topic hidden
#define NCLS 5
#define D2  300   // 2*H

#define MM    (BB*TT)   // 65536 GEMM rows
#define KPAD  320       // K padded
#define NPAD  1024      // 2 dirs x 512 padded cols

// ---------------- scratch (device globals; no allocations allowed) ----------
__device__ __half g_gih[2][TT][BB][G3];   // input projections fp16 (118 MB)
__device__ float g_seq[BB][TT][D2];       // bi-GRU outputs
__device__ float g_hidden[BB][D2];        // final hidden states
__device__ float g_ctxbase[KK][D2];       // batch-independent part of context
__device__ float g_context[BB][KK][D2];   // tanh context
__device__ float g_regpart[BB];
__device__ __half g_xh[(size_t)MM * KPAD];   // fp16 x, padded (40 MB)
__device__ __half g_wp[(size_t)NPAD * KPAD]; // fp16 Wih both dirs, padded
__device__ float  g_bihp[NPAD];              // padded bias (both dirs)

// ===================== PTX helpers ==========================================
__device__ __forceinline__ uint32_t smem_u32(const void* p) {
    uint32_t a;
    asm("{ .reg .u64 t; cvta.to.shared.u64 t, %1; cvt.u32.u64 %0, t; }" : "=r"(a) : "l"(p));
    return a;
}
__device__ __forceinline__ void cpasync16(uint32_t dst, const void* src) {
    asm volatile("cp.async.cg.shared.global [%0], [%1], 16;" :: "r"(dst), "l"(src));
}
__device__ __forceinline__ void cp_commit() { asm volatile("cp.async.commit_group;" ::: "memory"); }
template<int N> __device__ __forceinline__ void cp_waitg() {
    asm volatile("cp.async.wait_group %0;" :: "n"(N) : "memory");
}
__device__ __forceinline__ void ldm4(uint32_t* r, uint32_t addr) {
    asm volatile("ldmatrix.sync.aligned.m8n8.x4.shared.b16 {%0,%1,%2,%3}, [%4];"
                 : "=r"(r[0]), "=r"(r[1]), "=r"(r[2]), "=r"(r[3]) : "r"(addr));
}
__device__ __forceinline__ void ldm2(uint32_t* r, uint32_t addr) {
    asm volatile("ldmatrix.sync.aligned.m8n8.x2.shared.b16 {%0,%1}, [%2];"
                 : "=r"(r[0]), "=r"(r[1]) : "r"(addr));
}
__device__ __forceinline__ void mma16816(float* d, const uint32_t* a, uint32_t b0, uint32_t b1) {
    asm volatile("mma.sync.aligned.m16n8k16.row.col.f32.f16.f16.f32 "
                 "{%0,%1,%2,%3}, {%4,%5,%6,%7}, {%8,%9}, {%0,%1,%2,%3};"
                 : "+f"(d[0]), "+f"(d[1]), "+f"(d[2]), "+f"(d[3])
                 : "r"(a[0]), "r"(a[1]), "r"(a[2]), "r"(a[3]), "r"(b0), "r"(b1));
}
__device__ __forceinline__ float fast_sigmoid(float x) {
    float e, r;
    asm("ex2.approx.f32 %0, %1;" : "=f"(e) : "f"(-1.4426950408889634f * x));
    asm("rcp.approx.f32 %0, %1;" : "=f"(r) : "f"(1.0f + e));
    return r;
}
__device__ __forceinline__ float fast_tanh(float x) {
    float e, r;
    asm("ex2.approx.f32 %0, %1;" : "=f"(e) : "f"(2.8853900817779268f * x));
    asm("rcp.approx.f32 %0, %1;" : "=f"(r) : "f"(1.0f + e));
    return 1.0f - 2.0f * r;
}

// ===================== conversion kernels ===================================
__global__ void k_convA(const float* __restrict__ x) {
    int i = blockIdx.x * 256 + threadIdx.x;
    if (i >= MM * (KPAD / 2)) return;
    int m = i / (KPAD / 2), c2 = i % (KPAD / 2), k = c2 * 2;
    float a = (k < II)     ? x[(size_t)m * II + k]     : 0.f;
    float b = (k + 1 < II) ? x[(size_t)m * II + k + 1] : 0.f;
    ((__half2*)g_xh)[(size_t)m * (KPAD / 2) + c2] = __floats2half2_rn(a, b);
}
__global__ void k_convB(const float* __restrict__ Wf, const float* __restrict__ Wb) {
    int i = blockIdx.x * 256 + threadIdx.x;
    if (i >= NPAD * (KPAD / 2)) return;
    int jg = i / (KPAD / 2), c2 = i % (KPAD / 2), k = c2 * 2;
    int dir = jg >> 9, j = jg & 511;
    const float* W = dir ? Wb : Wf;
    float a = 0.f, b = 0.f;
    if (j < G3) {
        if (k < II)     a = W[(size_t)j * II + k];
        if (k + 1 < II) b = W[(size_t)j * II + k + 1];
    }
    ((__half2*)g_wp)[(size_t)jg * (KPAD / 2) + c2] = __floats2half2_rn(a, b);
}
__global__ void k_convBias(const float* __restrict__ bf, const float* __restrict__ bb) {
    int jg = blockIdx.x * 256 + threadIdx.x;
    if (jg >= NPAD) return;
    int dir = jg >> 9, j = jg & 511;
    g_bihp[jg] = (j < G3) ? (dir ? bb[j] : bf[j]) : 0.f;
}

// ===================== K1: mma.sync GEMM gi = x @ W^T + b ===================
#define BM  128
#define BN  128
#define BKC 32
#define LDA 40                // halves per smem row (32 + 8 pad)
#define NSTG (KPAD / BKC)     // 10 k-stages
#define PSTG 4                // pipeline depth
#define STG_BYTES ((BM + BN) * LDA * 2)       // 20480 B per stage
#define GEMM_SMEM (PSTG * STG_BYTES)          // 81920 B

__global__ void __launch_bounds__(256, 2) k_gemm() {
    extern __shared__ __align__(16) char gsm[];

    const int tid = threadIdx.x, wid = tid >> 5, lane = tid & 31;
    const int wm = wid & 3, wn = wid >> 2;
    const int m0 = blockIdx.x * BM, n0 = blockIdx.y * BN;

    float acc[2][8][4];
#pragma unroll
    for (int mi = 0; mi < 2; mi++)
#pragma unroll
        for (int nj = 0; nj < 8; nj++)
#pragma unroll
            for (int e = 0; e < 4; e++) acc[mi][nj][e] = 0.f;

    uint32_t sAb[PSTG], sBb[PSTG];
#pragma unroll
    for (int s = 0; s < PSTG; s++) {
        sAb[s] = smem_u32(gsm + s * STG_BYTES);
        sBb[s] = sAb[s] + BM * LDA * 2;
    }

    auto load_stage = [&](int ks, int buf) {
        int k0 = ks * BKC;
#pragma unroll
        for (int i = 0; i < 2; i++) {
            int idx = tid + i * 256;
            int row = idx >> 2, seg = idx & 3;
            cpasync16(sAb[buf] + (uint32_t)(row * LDA + seg * 8) * 2,
                      g_xh + (size_t)(m0 + row) * KPAD + k0 + seg * 8);
            cpasync16(sBb[buf] + (uint32_t)(row * LDA + seg * 8) * 2,
                      g_wp + (size_t)(n0 + row) * KPAD + k0 + seg * 8);
        }
    };

    load_stage(0, 0); cp_commit();
    load_stage(1, 1); cp_commit();
    load_stage(2, 2); cp_commit();

    const int a_row = (lane & 15);
    const int a_col8 = (lane >> 4) * 8;
    const int b_nrow = ((lane >> 4) * 8) + (lane & 7);
    const int b_col8 = ((lane >> 3) & 1) * 8;

#pragma unroll
    for (int ks = 0; ks < NSTG; ks++) {
        if (ks <= NSTG - 3)      cp_waitg<2>();
        else if (ks == NSTG - 2) cp_waitg<1>();
        else                     cp_waitg<0>();
        __syncthreads();
        if (ks + 3 < NSTG) { load_stage(ks + 3, (ks + 3) & 3); cp_commit(); }
        int buf = ks & 3;
#pragma unroll
        for (int s = 0; s < 2; s++) {
            uint32_t a[2][4], bfr[4][4];
#pragma unroll
            for (int mi = 0; mi < 2; mi++) {
                uint32_t addr = sAb[buf] +
                    (uint32_t)(((wm * 32 + mi * 16 + a_row) * LDA) + s * 16 + a_col8) * 2;
                ldm4(a[mi], addr);
            }
#pragma unroll
            for (int nj = 0; nj < 4; nj++) {
                uint32_t addr = sBb[buf] +
                    (uint32_t)(((wn * 64 + nj * 16 + b_nrow) * LDA) + s * 16 + b_col8) * 2;
                ldm4(bfr[nj], addr);
            }
#pragma unroll
            for (int mi = 0; mi < 2; mi++)
#pragma unroll
                for (int nj = 0; nj < 4; nj++) {
                    mma16816(acc[mi][2 * nj],     a[mi], bfr[nj][0], bfr[nj][1]);
                    mma16816(acc[mi][2 * nj + 1], a[mi], bfr[nj][2], bfr[nj][3]);
                }
        }
    }

    const int g = lane >> 2, tig = lane & 3;
#pragma unroll
    for (int mi = 0; mi < 2; mi++)
#pragma unroll
        for (int nj = 0; nj < 8; nj++) {
            int coln = wn * 64 + nj * 8 + tig * 2;
            int jglob = n0 + coln;
            int dir = jglob >> 9, jj = jglob & 511;
            if (jj < G3) {
                float bia0 = g_bihp[jglob], bia1 = g_bihp[jglob + 1];
#pragma unroll
                for (int h = 0; h < 2; h++) {
                    int m = m0 + wm * 32 + mi * 16 + g + h * 8;
                    int b = m >> 9, t = m & 511;
                    int ts = dir ? (TT - 1 - t) : t;
                    *(__half2*)&g_gih[dir][ts][b][jj] =
                        __floats2half2_rn(acc[mi][nj][2 * h] + bia0,
                                          acc[mi][nj][2 * h + 1] + bia1);
                }
            }
        }
}

// ======================= K2: GRU recurrence (fused, register-lean) ==========
// 128 CTAs (dir*64 + pair), 480 threads = 15 warps. Whh rows PERMUTED so that
// warp w's 32 rows are the (r,z,n) triples of gates jj in [10w,10w+10):
//   rloc g / g+8 / g+16 (g<8) -> r/z/n of gate 10w+g (all on lane 4g's accs)
//   rloc 24..29              -> r8,z8,n8,r9,z9,n9 (gates 8,9 -> lanes 1,2 via shfl)
// Coalesced smem staging for A-fragment load (reused as h double-buffer).
// ONE barrier per step; gates in-register; gi prefetch packed in 3 half2 regs.
#define LDS_H 168
#define REC_SMEM (480 * LDS_H * 2)          // 161280 B staging (h buffers reuse it)

__device__ __forceinline__ int maprow(int w, int rloc) {
    if (rloc < 24) return 10 * w + (rloc & 7) + HH * (rloc >> 3);
    if (rloc < 30) { int s = rloc - 24; return 10 * w + 8 + (s / 3) + HH * (s % 3); }
    return -1;
}

__global__ void __launch_bounds__(480, 1) k_rec(
    const float* __restrict__ Whh_f, const float* __restrict__ bhh_f,
    const float* __restrict__ Whh_b, const float* __restrict__ bhh_b)
{
    extern __shared__ __align__(16) char rsm[];
    __half* stg = (__half*)rsm;                          // staging (init only)
    __half (*sh)[8][LDS_H] = (__half (*)[8][LDS_H])rsm;  // h double-buffer (reuse)

    const int tid = threadIdx.x, wid = tid >> 5, lane = tid & 31;
    const int blk = blockIdx.x;
    const int dir = blk >> 6;
    const int b0  = (blk & 63) * 2;
    const float* Whh = dir ? Whh_b : Whh_f;
    const float* bhh = dir ? bhh_b : bhh_f;

    // ---- stage permuted Whh (coalesced in k), zero-padded ----
    for (int idx = tid; idx < 480 * LDS_H; idx += 480) {
        int j = idx / LDS_H, k = idx - j * LDS_H;
        int src = maprow(j >> 5, j & 31);
        stg[idx] = __float2half((src >= 0 && k < HH) ? Whh[src * HH + k] : 0.f);
    }
    __syncthreads();

    // ---- load A fragments (once) ----
    const int g = lane >> 2;
    const int a_row = lane & 15, a_col8 = (lane >> 4) * 8;
    uint32_t afr[2][10][4];
#pragma unroll
    for (int mt = 0; mt < 2; mt++)
#pragma unroll
        for (int kt = 0; kt < 10; kt++) {
            uint32_t addr = smem_u32(stg) +
                (uint32_t)(((wid * 32 + mt * 16 + a_row) * LDS_H) + kt * 16 + a_col8) * 2;
            ldm4(afr[mt][kt], addr);
        }
    float bias[4];
#pragma unroll
    for (int e = 0; e < 4; e++) {
        int r = maprow(wid, e * 8 + g);
        bias[e] = (r >= 0) ? bhh[r] : 0.f;
    }
    __syncthreads();                 // all frags loaded; staging now dead

    // ---- zero h double-buffer (overlays staging) ----
    for (int idx = tid; idx < 2 * 8 * LDS_H; idx += 480)
        ((__half*)sh)[idx] = __float2half(0.f);

    // B (h) ldmatrix lane addresses, both buffers
    int hrow = (lane < 8) ? lane : ((lane < 16) ? (lane - 8) : 0);
    int hcol = (lane >= 8 && lane < 16) ? 8 : 0;
    const uint32_t hb0 = smem_u32(&sh[0][hrow][hcol]);
    const uint32_t hb1 = smem_u32(&sh[1][hrow][hcol]);

    // gate lanes: lane%4==0 own gate 10w+g; lanes 1,2 own gates 10w+8, 10w+9
    const bool isg = (lane & 3) == 0;
    const bool gl  = isg || (lane == 1) || (lane == 2);
    const int  jmine = isg ? (10 * wid + g) : (10 * wid + 7 + lane);
    const unsigned FULL = 0xffffffffu;
    const int sR = (lane == 1) ? 0 : ((lane == 2) ? 12 : lane);
    const int sZ = (lane == 1) ? 4 : ((lane == 2) ? 16 : lane);
    const int sN = (lane == 1) ? 8 : ((lane == 2) ? 20 : lane);

    // gi prefetch: 6 halves packed into 3 half2 regs (b0 row in .x, b0+1 in .y)
    const __half* gi = &g_gih[dir][0][0][0];
    __half2 pa, pb, pc;
    if (gl) {
        long o = (long)b0 * G3 + jmine;
        pa = __halves2half2(gi[o],          gi[o + G3]);
        pb = __halves2half2(gi[o + HH],     gi[o + G3 + HH]);
        pc = __halves2half2(gi[o + 2 * HH], gi[o + G3 + 2 * HH]);
    }
    float h0 = 0.f, h1 = 0.f;
    __syncthreads();                 // h[0], h[1] zeroed

    for (int t = 0; t < TT; t++) {
        const uint32_t hbp = (t & 1) ? hb1 : hb0;
        float a0[4] = { bias[0], bias[0], bias[1], bias[1] };
        float a1[4] = { bias[2], bias[2], bias[3], bias[3] };
#pragma unroll
        for (int kt = 0; kt < 10; kt++) {
            uint32_t bfr[2];
            ldm2(bfr, hbp + kt * 32);
            mma16816(a0, afr[0][kt], bfr[0], bfr[1]);
            mma16816(a1, afr[1][kt], bfr[0], bfr[1]);
        }
        // route gates 8,9 (rows 24..29 live in a1[2],a1[3] of lanes 0..20)
        float er0 = __shfl_sync(FULL, a1[2], sR), er1 = __shfl_sync(FULL, a1[3], sR);
        float ez0 = __shfl_sync(FULL, a1[2], sZ), ez1 = __shfl_sync(FULL, a1[3], sZ);
        float en0 = __shfl_sync(FULL, a1[2], sN), en1 = __shfl_sync(FULL, a1[3], sN);

        if (gl) {
            float2 fr = __half22float2(pa), fz = __half22float2(pb), fn = __half22float2(pc);
            if (t + 1 < TT) {
                long o = ((long)(t + 1) * BB + b0) * G3 + jmine;
                pa = __halves2half2(gi[o],          gi[o + G3]);
                pb = __halves2half2(gi[o + HH],     gi[o + G3 + HH]);
                pc = __halves2half2(gi[o + 2 * HH], gi[o + G3 + 2 * HH]);
            }
            float gr0, gr1, gz0, gz1, gn0, gn1;
            if (isg) { gr0 = a0[0]; gr1 = a0[1]; gz0 = a0[2]; gz1 = a0[3];
                       gn0 = a1[0]; gn1 = a1[1]; }
            else     { gr0 = er0;   gr1 = er1;   gz0 = ez0;   gz1 = ez1;
                       gn0 = en0;   gn1 = en1; }
            float r0 = fast_sigmoid(gr0 + fr.x);
            float z0 = fast_sigmoid(gz0 + fz.x);
            float n0 = fast_tanh(fn.x + r0 * gn0);
            h0 = (1.f - z0) * n0 + z0 * h0;
            float r1 = fast_sigmoid(gr1 + fr.y);
            float z1 = fast_sigmoid(gz1 + fz.y);
            float n1 = fast_tanh(fn.y + r1 * gn1);
            h1 = (1.f - z1) * n1 + z1 * h1;
            int nxt = (t & 1) ^ 1;
            sh[nxt][0][jmine] = __float2half(h0);
            sh[nxt][1][jmine] = __float2half(h1);
            int tw = dir ? (TT - 1 - t) : t;
            g_seq[b0][tw][dir * HH + jmine]     = h0;
            g_seq[b0 + 1][tw][dir * HH + jmine] = h1;
        }
        __syncthreads();   // h[nxt] complete; all done reading h[par]
    }
    if (gl) {
        g_hidden[b0][dir * HH + jmine]     = h0;
        g_hidden[b0 + 1][dir * HH + jmine] = h1;
    }
}

// ============== K3a: batch-independent part of attention context ============
__global__ void k_ctxbase(const float* __restrict__ ac, const float* __restrict__ Wattn,
                          const float* __restrict__ battn)
{
    int k = blockIdx.x;
    __shared__ float sac[CC];
    int tid = threadIdx.x;
    if (tid < CC) sac[tid] = ac[k * CC + tid];
    __syncthreads();
    if (tid < D2) {
        float acc = battn[k * D2 + tid];
        const float* W = Wattn + (long)k * (CC + D2) * D2 + tid;
        for (int c = 0; c < CC; c++) acc = fmaf(sac[c], W[(long)c * D2], acc);
        g_ctxbase[k][tid] = acc;
    }
}

// ============== K3b: context = tanh(base + hidden @ Wattn[:,C:,:]) ==========
__global__ void k_context(const float* __restrict__ Wattn)
{
    int k = blockIdx.x, b = blockIdx.y;
    __shared__ float shid[D2];
    int tid = threadIdx.x;
    if (tid < D2) shid[tid] = g_hidden[b][tid];
    __syncthreads();
    if (tid < D2) {
        float acc = g_ctxbase[k][tid];
        const float* W = Wattn + ((long)k * (CC + D2) + CC) * D2 + tid;
        for (int e = 0; e < D2; e++) acc = fmaf(shid[e], W[(long)e * D2], acc);
        g_context[b][k][tid] = tanhf(acc);
    }
}

// ============== K3c: fused attention + topic + classifier + reg part ========
#define TS 16
__global__ void k_attn(const float* __restrict__ Wtop, const float* __restrict__ btop,
                       const float* __restrict__ Wout, const float* __restrict__ bout,
                       float* __restrict__ out)
{
    int b = blockIdx.x;
    __shared__ float sctx[KK][D2];
    __shared__ float sE[TT][KK];
    __shared__ float sSeq[TS][D2];
    __shared__ float spool[KK][D2];
    __shared__ float sfeat[KK * THD];
    __shared__ float sred[256];
    __shared__ float snorm[KK];
    __shared__ float slog[NCLS];
    int tid = threadIdx.x;

    for (int i = tid; i < KK * D2; i += 256) sctx[i / D2][i % D2] = g_context[b][i / D2][i % D2];
    __syncthreads();

    for (int tile = 0; tile < TT / TS; tile++) {
        int t0 = tile * TS;
        for (int i = tid; i < TS * D2; i += 256)
            sSeq[i / D2][i % D2] = g_seq[b][t0 + i / D2][i % D2];
        __syncthreads();
        if (tid < TS * KK) {
            int r = tid / KK, k = tid % KK;
            float acc = 0.f;
            for (int d = 0; d < D2; d++) acc = fmaf(sSeq[r][d], sctx[k][d], acc);
            sE[t0 + r][k] = acc;
        }
        __syncthreads();
    }

    for (int k = 0; k < KK; k++) {
        float m = -1e30f;
        for (int t = tid; t < TT; t += 256) m = fmaxf(m, sE[t][k]);
        sred[tid] = m; __syncthreads();
        for (int s = 128; s > 0; s >>= 1) { if (tid < s) sred[tid] = fmaxf(sred[tid], sred[tid + s]); __syncthreads(); }
        m = sred[0]; __syncthreads();
        float sum = 0.f;
        for (int t = tid; t < TT; t += 256) { float e = expf(sE[t][k] - m); sE[t][k] = e; sum += e; }
        sred[tid] = sum; __syncthreads();
        for (int s = 128; s > 0; s >>= 1) { if (tid < s) sred[tid] += sred[tid + s]; __syncthreads(); }
        float inv = 1.f / sred[0]; __syncthreads();
        for (int t = tid; t < TT; t += 256) sE[t][k] *= inv;
        __syncthreads();
    }

    float pacc[8];
#pragma unroll
    for (int i = 0; i < 8; i++) pacc[i] = 0.f;
    for (int tile = 0; tile < TT / TS; tile++) {
        int t0 = tile * TS;
        for (int i = tid; i < TS * D2; i += 256)
            sSeq[i / D2][i % D2] = g_seq[b][t0 + i / D2][i % D2];
        __syncthreads();
#pragma unroll
        for (int i = 0; i < 8; i++) {
            int idx = tid + i * 256;
            if (idx < KK * D2) {
                int k = idx / D2, d = idx % D2;
                float a = pacc[i];
#pragma unroll
                for (int r = 0; r < TS; r++) a = fmaf(sSeq[r][d], sE[t0 + r][k], a);
                pacc[i] = a;
            }
        }
        __syncthreads();
    }
#pragma unroll
    for (int i = 0; i < 8; i++) {
        int idx = tid + i * 256;
        if (idx < KK * D2) spool[idx / D2][idx % D2] = pacc[i];
    }
    __syncthreads();

    if (tid < KK * THD) {
        int k = tid / THD, hh = tid % THD;
        float acc = btop[k * THD + hh];
        const float* W = Wtop + ((long)k * D2) * THD + hh;
        for (int d = 0; d < D2; d++) acc = fmaf(spool[k][d], W[d * THD], acc);
        sfeat[tid] = fmaxf(acc, 0.f);
    }
    if (tid >= 128 && tid < 128 + KK) {
        int k = tid - 128;
        float s = 0.f;
        for (int d = 0; d < D2; d++) { float v = sctx[k][d]; s = fmaf(v, v, s); }
        snorm[k] = fmaxf(sqrtf(s), 1e-12f);
    }
    __syncthreads();

    if (tid < NCLS) {
        float acc = bout[tid];
        for (int f = 0; f < KK * THD; f++) acc = fmaf(sfeat[f], Wout[f * NCLS + tid], acc);
        slog[tid] = acc;
    }
    if (tid < 64) sred[tid] = 0.f;
    __syncthreads();
    if (tid < KK * KK) {
        int k = tid / KK, j = tid % KK;
        float acc = 0.f;
        for (int d = 0; d < D2; d++) acc = fmaf(sctx[k][d], sctx[j][d], acc);
        acc = acc / (snorm[k] * snorm[j]) - ((k == j) ? 1.f : 0.f);
        sred[tid] = acc * acc;
    }
    __syncthreads();
    if (tid == 0) {
        float m = slog[0];
        for (int c = 1; c < NCLS; c++) m = fmaxf(m, slog[c]);
        float s = 0.f, e[NCLS];
        for (int c = 0; c < NCLS; c++) { e[c] = expf(slog[c] - m); s += e[c]; }
        for (int c = 0; c < NCLS; c++) out[b * NCLS + c] = e[c] / s;
        float rs = 0.f;
        for (int i = 0; i < KK * KK; i++) rs += sred[i];
        g_regpart[b] = sqrtf(rs);
    }
}

// ============== K3d: reg = mean_b regpart =================================
__global__ void k_reg(float* __restrict__ out)
{
    __shared__ float sr[BB];
    int tid = threadIdx.x;
    sr[tid] = g_regpart[tid];
    __syncthreads();
    for (int s = 64; s > 0; s >>= 1) { if (tid < s) sr[tid] += sr[tid + s]; __syncthreads(); }
    if (tid == 0) out[BB * NCLS] = sr[0] / (float)BB;
}

// ===========================================================================
extern "C" void kernel_launch(void* const* d_in, const int* in_sizes, int n_in,
                              void* d_out, int out_size)
{
    const float* x      = (const float*)d_in[0];
    const float* Wih_f  = (const float*)d_in[1];
    const float* Whh_f  = (const float*)d_in[2];
    const float* bih_f  = (const float*)d_in[3];
    const float* bhh_f  = (const float*)d_in[4];
    const float* Wih_b  = (const float*)d_in[5];
    const float* Whh_b  = (const float*)d_in[6];
    const float* bih_b  = (const float*)d_in[7];
    const float* bhh_b  = (const float*)d_in[8];
    const float* ac     = (const float*)d_in[9];
    const float* Wattn  = (const float*)d_in[10];
    const float* battn  = (const float*)d_in[11];
    const float* Wtop   = (const float*)d_in[12];
    const float* btop   = (const float*)d_in[13];
    const float* Wout   = (const float*)d_in[14];
    const float* bout   = (const float*)d_in[15];
    float* out = (float*)d_out;

    cudaFuncSetAttribute(k_gemm, cudaFuncAttributeMaxDynamicSharedMemorySize, GEMM_SMEM);
    cudaFuncSetAttribute(k_rec,  cudaFuncAttributeMaxDynamicSharedMemorySize, REC_SMEM);

    k_convA<<<(MM * (KPAD / 2) + 255) / 256, 256>>>(x);
    k_convB<<<(NPAD * (KPAD / 2) + 255) / 256, 256>>>(Wih_f, Wih_b);
    k_convBias<<<(NPAD + 255) / 256, 256>>>(bih_f, bih_b);
    k_gemm<<<dim3(MM / BM, NPAD / BN), 256, GEMM_SMEM>>>();
    k_rec<<<128, 480, REC_SMEM>>>(Whh_f, bhh_f, Whh_b, bhh_b);
    k_ctxbase<<<KK, 320>>>(ac, Wattn, battn);
    k_context<<<dim3(KK, BB), 320>>>(Wattn);
    k_attn<<<BB, 256>>>(Wtop, btop, Wout, bout, out);
    k_reg<<<1, BB>>>(out);
}

// round 15
// speedup vs baseline: 1.6027x; 1.6027x over previous
#include <cuda_runtime.h>
#include <cuda_fp16.h>
#include <math.h>
#include <stdint.h>

#define BB  128   // batch
#define TT  512   // time
#define II  300   // input dim
#define HH  150   // hidden per dir
#define G3  450   // 3*H
#define KK  6     // topics
#define CC  300   // attn context dim
#define THD 20    // topic hidden
#define NCLS 5
#define D2  300   // 2*H

#define MM    (BB*TT)   // 65536 GEMM rows
#define KPAD  320       // K padded
#define NPAD  1024      // 2 dirs x 512 padded cols

// ---------------- scratch (device globals; no allocations allowed) ----------
__device__ __half g_gih[2][TT][BB][G3];   // input projections fp16 (118 MB)
__device__ float g_seq[BB][TT][D2];       // bi-GRU outputs
__device__ float g_hidden[BB][D2];        // final hidden states
__device__ float g_ctxbase[KK][D2];       // batch-independent part of context
__device__ float g_context[BB][KK][D2];   // tanh context
__device__ float g_regpart[BB];
__device__ __half g_xh[(size_t)MM * KPAD];   // fp16 x, padded (40 MB)
__device__ __half g_wp[(size_t)NPAD * KPAD]; // fp16 Wih both dirs, padded
__device__ float  g_bihp[NPAD];              // padded bias (both dirs)

// ===================== PTX helpers ==========================================
__device__ __forceinline__ uint32_t smem_u32(const void* p) {
    uint32_t a;
    asm("{ .reg .u64 t; cvta.to.shared.u64 t, %1; cvt.u32.u64 %0, t; }" : "=r"(a) : "l"(p));
    return a;
}
__device__ __forceinline__ void cpasync16(uint32_t dst, const void* src) {
    asm volatile("cp.async.cg.shared.global [%0], [%1], 16;" :: "r"(dst), "l"(src));
}
__device__ __forceinline__ void cp_commit() { asm volatile("cp.async.commit_group;" ::: "memory"); }
template<int N> __device__ __forceinline__ void cp_waitg() {
    asm volatile("cp.async.wait_group %0;" :: "n"(N) : "memory");
}
__device__ __forceinline__ void ldm4(uint32_t* r, uint32_t addr) {
    asm volatile("ldmatrix.sync.aligned.m8n8.x4.shared.b16 {%0,%1,%2,%3}, [%4];"
                 : "=r"(r[0]), "=r"(r[1]), "=r"(r[2]), "=r"(r[3]) : "r"(addr));
}
__device__ __forceinline__ void ldm2(uint32_t* r, uint32_t addr) {
    asm volatile("ldmatrix.sync.aligned.m8n8.x2.shared.b16 {%0,%1}, [%2];"
                 : "=r"(r[0]), "=r"(r[1]) : "r"(addr));
}
__device__ __forceinline__ void mma16816(float* d, const uint32_t* a, uint32_t b0, uint32_t b1) {
    asm volatile("mma.sync.aligned.m16n8k16.row.col.f32.f16.f16.f32 "
                 "{%0,%1,%2,%3}, {%4,%5,%6,%7}, {%8,%9}, {%0,%1,%2,%3};"
                 : "+f"(d[0]), "+f"(d[1]), "+f"(d[2]), "+f"(d[3])
                 : "r"(a[0]), "r"(a[1]), "r"(a[2]), "r"(a[3]), "r"(b0), "r"(b1));
}
__device__ __forceinline__ float fast_sigmoid(float x) {
    float e, r;
    asm("ex2.approx.f32 %0, %1;" : "=f"(e) : "f"(-1.4426950408889634f * x));
    asm("rcp.approx.f32 %0, %1;" : "=f"(r) : "f"(1.0f + e));
    return r;
}
__device__ __forceinline__ float fast_tanh(float x) {
    float e, r;
    asm("ex2.approx.f32 %0, %1;" : "=f"(e) : "f"(2.8853900817779268f * x));
    asm("rcp.approx.f32 %0, %1;" : "=f"(r) : "f"(1.0f + e));
    return 1.0f - 2.0f * r;
}

// ===================== conversion kernels ===================================
__global__ void k_convA(const float* __restrict__ x) {
    int i = blockIdx.x * 256 + threadIdx.x;
    if (i >= MM * (KPAD / 2)) return;
    int m = i / (KPAD / 2), c2 = i % (KPAD / 2), k = c2 * 2;
    float a = (k < II)     ? x[(size_t)m * II + k]     : 0.f;
    float b = (k + 1 < II) ? x[(size_t)m * II + k + 1] : 0.f;
    ((__half2*)g_xh)[(size_t)m * (KPAD / 2) + c2] = __floats2half2_rn(a, b);
}
__global__ void k_convB(const float* __restrict__ Wf, const float* __restrict__ Wb,
                        const float* __restrict__ bf, const float* __restrict__ bb) {
    int i = blockIdx.x * 256 + threadIdx.x;
    if (i >= NPAD * (KPAD / 2)) return;
    int jg = i / (KPAD / 2), c2 = i % (KPAD / 2), k = c2 * 2;
    int dir = jg >> 9, j = jg & 511;
    const float* W = dir ? Wb : Wf;
    float a = 0.f, b = 0.f;
    if (j < G3) {
        if (k < II)     a = W[(size_t)j * II + k];
        if (k + 1 < II) b = W[(size_t)j * II + k + 1];
    }
    ((__half2*)g_wp)[(size_t)jg * (KPAD / 2) + c2] = __floats2half2_rn(a, b);
    if (c2 == 0)
        g_bihp[jg] = (j < G3) ? (dir ? bb[j] : bf[j]) : 0.f;
}

// ===================== K1: mma.sync GEMM gi = x @ W^T + b ===================
// CTA 128x128, BK=64, 3-buffer cp.async pipeline, ONE barrier per k-stage (5).
#define BM  128
#define BN  128
#define BKC 64
#define LDA 72                // halves per smem row (64 + 8 pad); 144 B
#define NSTG (KPAD / BKC)     // 5 k-stages
#define PSTG 3                // buffers
#define STG_BYTES ((BM + BN) * LDA * 2)       // 36864 B per stage
#define GEMM_SMEM (PSTG * STG_BYTES)          // 110592 B

__global__ void __launch_bounds__(256, 2) k_gemm() {
    extern __shared__ __align__(16) char gsm[];

    const int tid = threadIdx.x, wid = tid >> 5, lane = tid & 31;
    const int wm = wid & 3, wn = wid >> 2;
    const int m0 = blockIdx.x * BM, n0 = blockIdx.y * BN;

    float acc[2][8][4];
#pragma unroll
    for (int mi = 0; mi < 2; mi++)
#pragma unroll
        for (int nj = 0; nj < 8; nj++)
#pragma unroll
            for (int e = 0; e < 4; e++) acc[mi][nj][e] = 0.f;

    uint32_t sAb[PSTG], sBb[PSTG];
#pragma unroll
    for (int s = 0; s < PSTG; s++) {
        sAb[s] = smem_u32(gsm + s * STG_BYTES);
        sBb[s] = sAb[s] + BM * LDA * 2;
    }

    auto load_stage = [&](int ks, int buf) {
        int k0 = ks * BKC;
#pragma unroll
        for (int i = 0; i < 4; i++) {                 // 1024 segs per matrix
            int idx = tid + i * 256;
            int row = idx >> 3, seg = idx & 7;
            cpasync16(sAb[buf] + (uint32_t)(row * LDA + seg * 8) * 2,
                      g_xh + (size_t)(m0 + row) * KPAD + k0 + seg * 8);
            cpasync16(sBb[buf] + (uint32_t)(row * LDA + seg * 8) * 2,
                      g_wp + (size_t)(n0 + row) * KPAD + k0 + seg * 8);
        }
    };

    load_stage(0, 0); cp_commit();
    load_stage(1, 1); cp_commit();

    const int a_row = (lane & 15);
    const int a_col8 = (lane >> 4) * 8;
    const int b_nrow = ((lane >> 4) * 8) + (lane & 7);
    const int b_col8 = ((lane >> 3) & 1) * 8;

#pragma unroll
    for (int ks = 0; ks < NSTG; ks++) {
        if (ks < NSTG - 1) cp_waitg<1>(); else cp_waitg<0>();
        __syncthreads();              // stage ks visible; buf (ks+2)%3 free
        if (ks + 2 < NSTG) { load_stage(ks + 2, (ks + 2) % 3); cp_commit(); }
        int buf = ks % 3;
#pragma unroll
        for (int s = 0; s < 4; s++) {                 // four k16 steps
            uint32_t a[2][4], bfr[4][4];
#pragma unroll
            for (int mi = 0; mi < 2; mi++) {
                uint32_t addr = sAb[buf] +
                    (uint32_t)(((wm * 32 + mi * 16 + a_row) * LDA) + s * 16 + a_col8) * 2;
                ldm4(a[mi], addr);
            }
#pragma unroll
            for (int nj = 0; nj < 4; nj++) {
                uint32_t addr = sBb[buf] +
                    (uint32_t)(((wn * 64 + nj * 16 + b_nrow) * LDA) + s * 16 + b_col8) * 2;
                ldm4(bfr[nj], addr);
            }
#pragma unroll
            for (int mi = 0; mi < 2; mi++)
#pragma unroll
                for (int nj = 0; nj < 4; nj++) {
                    mma16816(acc[mi][2 * nj],     a[mi], bfr[nj][0], bfr[nj][1]);
                    mma16816(acc[mi][2 * nj + 1], a[mi], bfr[nj][2], bfr[nj][3]);
                }
        }
    }

    // ---- epilogue: bias + fp16 scatter to g_gih ----------------------------
    const int g = lane >> 2, tig = lane & 3;
#pragma unroll
    for (int mi = 0; mi < 2; mi++)
#pragma unroll
        for (int nj = 0; nj < 8; nj++) {
            int coln = wn * 64 + nj * 8 + tig * 2;
            int jglob = n0 + coln;
            int dir = jglob >> 9, jj = jglob & 511;
            if (jj < G3) {
                float bia0 = g_bihp[jglob], bia1 = g_bihp[jglob + 1];
#pragma unroll
                for (int h = 0; h < 2; h++) {
                    int m = m0 + wm * 32 + mi * 16 + g + h * 8;
                    int b = m >> 9, t = m & 511;
                    int ts = dir ? (TT - 1 - t) : t;
                    *(__half2*)&g_gih[dir][ts][b][jj] =
                        __floats2half2_rn(acc[mi][nj][2 * h] + bia0,
                                          acc[mi][nj][2 * h + 1] + bia1);
                }
            }
        }
}

// ======================= K2: GRU recurrence (tensor-core, R11 design) =======
// 128 CTAs (dir*64 + pair), 480 threads = 15 warps. Warp w owns output rows
// [32w, 32w+32) as register-resident mma A-fragments (2 m-tiles x 10 k-tiles).
// Per step: h (8x168 fp16 smem, rows=batch padded to 8) -> 10 ldmatrix.x2 +
// 20 mma.sync with bias-initialized accumulators; lanes with lane%4==0 scatter
// gh cols 0,1 (the two live batch rows) to smem; gate threads finish.
#define RROWS 480                 // 15 warps * 32 rows (450 live)
#define LDS_W 168                 // halves per staging row
#define WSTG_BYTES (RROWS * LDS_W * 2)        // 161280
#define RH_OFF   WSTG_BYTES                   // h: 8 x 168 halves = 2688 B
#define RGH_OFF  (RH_OFF + 2688)              // gh: 2 x 480 floats = 3840 B
#define REC_SMEM (RGH_OFF + 3840)             // 167808 B

__global__ void __launch_bounds__(480, 1) k_rec(
    const float* __restrict__ Whh_f, const float* __restrict__ bhh_f,
    const float* __restrict__ Whh_b, const float* __restrict__ bhh_b)
{
    extern __shared__ __align__(16) char smem[];
    __half* sWst = (__half*)smem;                       // staging (init only)
    __half* sh   = (__half*)(smem + RH_OFF);            // [8][168]
    float*  sgh  = (float*)(smem + RGH_OFF);            // [2][480]

    const int tid  = threadIdx.x, wid = tid >> 5, lane = tid & 31;
    const int blk  = blockIdx.x;
    const int dir  = blk >> 6;
    const int b0   = (blk & 63) * 2;
    const float* Whh = dir ? Whh_b : Whh_f;
    const float* bhh = dir ? bhh_b : bhh_f;

    // ---- init: stage Whh fp16 padded [480][168], zero h ----
    for (int idx = tid; idx < RROWS * LDS_W; idx += 480) {
        int j = idx / LDS_W, k = idx - j * LDS_W;
        sWst[j * LDS_W + k] = __float2half(
            (j < G3 && k < HH) ? Whh[j * HH + k] : 0.f);
    }
    for (int idx = tid; idx < 8 * LDS_W; idx += 480)
        sh[idx] = __float2half(0.f);
    __syncthreads();

    // ---- load A fragments into registers (once) ----
    const int a_row = lane & 15, a_col8 = (lane >> 4) * 8;
    uint32_t afr[2][10][4];
#pragma unroll
    for (int mt = 0; mt < 2; mt++)
#pragma unroll
        for (int kt = 0; kt < 10; kt++) {
            uint32_t addr = smem_u32(sWst) +
                (uint32_t)(((wid * 32 + mt * 16 + a_row) * LDS_W) + kt * 16 + a_col8) * 2;
            ldm4(afr[mt][kt], addr);
        }

    // bias registers for accumulator init (rows g, g+8 per m-tile)
    const int g = lane >> 2;
    float bias[2][2];
#pragma unroll
    for (int mt = 0; mt < 2; mt++) {
        int r = wid * 32 + mt * 16 + g;
        bias[mt][0] = (r < G3) ? bhh[r] : 0.f;
        bias[mt][1] = (r + 8 < G3) ? bhh[r + 8] : 0.f;
    }

    // B ldmatrix per-lane base address into h tile
    int hrow = (lane < 8) ? lane : ((lane < 16) ? (lane - 8) : 0);
    int hcol = (lane >= 8 && lane < 16) ? 8 : 0;
    const uint32_t hb = smem_u32(sh) + (uint32_t)(hrow * LDS_W + hcol) * 2;

    __syncthreads();   // A frags loaded; staging smem now dead

    // gi prefetch (gate threads: tid<300 -> (b, jj))
    const __half* gi_base = &g_gih[dir][0][0][0];
    const int gb = tid / HH, gj = tid - gb * HH;       // valid when tid<300
    __half pr, pz, pn;
    float hreg = 0.f;
    if (tid < 2 * HH) {
        long o = (long)(b0 + gb) * G3 + gj;
        pr = gi_base[o]; pz = gi_base[o + HH]; pn = gi_base[o + 2 * HH];
    }

    for (int t = 0; t < TT; t++) {
        // ---- matvec via tensor cores ----
        float acc0[4] = { bias[0][0], bias[0][0], bias[0][1], bias[0][1] };
        float acc1[4] = { bias[1][0], bias[1][0], bias[1][1], bias[1][1] };
#pragma unroll
        for (int kt = 0; kt < 10; kt++) {
            uint32_t bfr[2];
            ldm2(bfr, hb + kt * 32);                   // 16 k-halves, n rows 0-7
            mma16816(acc0, afr[0][kt], bfr[0], bfr[1]);
            mma16816(acc1, afr[1][kt], bfr[0], bfr[1]);
        }
        if ((lane & 3) == 0) {                         // cols 0,1 = batch rows
            int r0 = wid * 32 + g;
            sgh[r0]            = acc0[0]; sgh[480 + r0]      = acc0[1];
            sgh[r0 + 8]        = acc0[2]; sgh[480 + r0 + 8]  = acc0[3];
            sgh[r0 + 16]       = acc1[0]; sgh[480 + r0 + 16] = acc1[1];
            sgh[r0 + 24]       = acc1[2]; sgh[480 + r0 + 24] = acc1[3];
        }
        __syncthreads();                               // gh ready; h reads done

        // ---- gates ----
        if (tid < 2 * HH) {
            float gir = __half2float(pr), giz = __half2float(pz), gin = __half2float(pn);
            if (t + 1 < TT) {                          // prefetch next step
                long o = ((long)(t + 1) * BB + b0 + gb) * G3 + gj;
                pr = gi_base[o]; pz = gi_base[o + HH]; pn = gi_base[o + 2 * HH];
            }
            const float* ghb = sgh + gb * 480;
            float r = fast_sigmoid(ghb[gj] + gir);
            float z = fast_sigmoid(ghb[gj + HH] + giz);
            float n = fast_tanh(gin + r * ghb[gj + 2 * HH]);
            float hn = (1.f - z) * n + z * hreg;
            hreg = hn;
            sh[gb * LDS_W + gj] = __float2half(hn);
            int tw = dir ? (TT - 1 - t) : t;
            g_seq[b0 + gb][tw][dir * HH + gj] = hn;
        }
        __syncthreads();                               // h ready for next step
    }
    if (tid < 2 * HH)
        g_hidden[b0 + gb][dir * HH + gj] = hreg;
}

// ============== K3a: batch-independent part of attention context ============
__global__ void k_ctxbase(const float* __restrict__ ac, const float* __restrict__ Wattn,
                          const float* __restrict__ battn)
{
    int k = blockIdx.x;
    __shared__ float sac[CC];
    int tid = threadIdx.x;
    if (tid < CC) sac[tid] = ac[k * CC + tid];
    __syncthreads();
    if (tid < D2) {
        float acc = battn[k * D2 + tid];
        const float* W = Wattn + (long)k * (CC + D2) * D2 + tid;
        for (int c = 0; c < CC; c++) acc = fmaf(sac[c], W[(long)c * D2], acc);
        g_ctxbase[k][tid] = acc;
    }
}

// ============== K3b: context = tanh(base + hidden @ Wattn[:,C:,:]) ==========
__global__ void k_context(const float* __restrict__ Wattn)
{
    int k = blockIdx.x, b = blockIdx.y;
    __shared__ float shid[D2];
    int tid = threadIdx.x;
    if (tid < D2) shid[tid] = g_hidden[b][tid];
    __syncthreads();
    if (tid < D2) {
        float acc = g_ctxbase[k][tid];
        const float* W = Wattn + ((long)k * (CC + D2) + CC) * D2 + tid;
        for (int e = 0; e < D2; e++) acc = fmaf(shid[e], W[(long)e * D2], acc);
        g_context[b][k][tid] = tanhf(acc);
    }
}

// ============== K3c: fused attention + topic + classifier + reg part ========
#define TS 16
__global__ void k_attn(const float* __restrict__ Wtop, const float* __restrict__ btop,
                       const float* __restrict__ Wout, const float* __restrict__ bout,
                       float* __restrict__ out)
{
    int b = blockIdx.x;
    __shared__ float sctx[KK][D2];
    __shared__ float sE[TT][KK];
    __shared__ float sSeq[TS][D2];
    __shared__ float spool[KK][D2];
    __shared__ float sfeat[KK * THD];
    __shared__ float sred[256];
    __shared__ float snorm[KK];
    __shared__ float slog[NCLS];
    int tid = threadIdx.x;

    for (int i = tid; i < KK * D2; i += 256) sctx[i / D2][i % D2] = g_context[b][i / D2][i % D2];
    __syncthreads();

    for (int tile = 0; tile < TT / TS; tile++) {
        int t0 = tile * TS;
        for (int i = tid; i < TS * D2; i += 256)
            sSeq[i / D2][i % D2] = g_seq[b][t0 + i / D2][i % D2];
        __syncthreads();
        if (tid < TS * KK) {
            int r = tid / KK, k = tid % KK;
            float acc = 0.f;
            for (int d = 0; d < D2; d++) acc = fmaf(sSeq[r][d], sctx[k][d], acc);
            sE[t0 + r][k] = acc;
        }
        __syncthreads();
    }

    for (int k = 0; k < KK; k++) {
        float m = -1e30f;
        for (int t = tid; t < TT; t += 256) m = fmaxf(m, sE[t][k]);
        sred[tid] = m; __syncthreads();
        for (int s = 128; s > 0; s >>= 1) { if (tid < s) sred[tid] = fmaxf(sred[tid], sred[tid + s]); __syncthreads(); }
        m = sred[0]; __syncthreads();
        float sum = 0.f;
        for (int t = tid; t < TT; t += 256) { float e = expf(sE[t][k] - m); sE[t][k] = e; sum += e; }
        sred[tid] = sum; __syncthreads();
        for (int s = 128; s > 0; s >>= 1) { if (tid < s) sred[tid] += sred[tid + s]; __syncthreads(); }
        float inv = 1.f / sred[0]; __syncthreads();
        for (int t = tid; t < TT; t += 256) sE[t][k] *= inv;
        __syncthreads();
    }

    float pacc[8];
#pragma unroll
    for (int i = 0; i < 8; i++) pacc[i] = 0.f;
    for (int tile = 0; tile < TT / TS; tile++) {
        int t0 = tile * TS;
        for (int i = tid; i < TS * D2; i += 256)
            sSeq[i / D2][i % D2] = g_seq[b][t0 + i / D2][i % D2];
        __syncthreads();
#pragma unroll
        for (int i = 0; i < 8; i++) {
            int idx = tid + i * 256;
            if (idx < KK * D2) {
                int k = idx / D2, d = idx % D2;
                float a = pacc[i];
#pragma unroll
                for (int r = 0; r < TS; r++) a = fmaf(sSeq[r][d], sE[t0 + r][k], a);
                pacc[i] = a;
            }
        }
        __syncthreads();
    }
#pragma unroll
    for (int i = 0; i < 8; i++) {
        int idx = tid + i * 256;
        if (idx < KK * D2) spool[idx / D2][idx % D2] = pacc[i];
    }
    __syncthreads();

    if (tid < KK * THD) {
        int k = tid / THD, hh = tid % THD;
        float acc = btop[k * THD + hh];
        const float* W = Wtop + ((long)k * D2) * THD + hh;
        for (int d = 0; d < D2; d++) acc = fmaf(spool[k][d], W[d * THD], acc);
        sfeat[tid] = fmaxf(acc, 0.f);
    }
    if (tid >= 128 && tid < 128 + KK) {
        int k = tid - 128;
        float s = 0.f;
        for (int d = 0; d < D2; d++) { float v = sctx[k][d]; s = fmaf(v, v, s); }
        snorm[k] = fmaxf(sqrtf(s), 1e-12f);
    }
    __syncthreads();

    if (tid < NCLS) {
        float acc = bout[tid];
        for (int f = 0; f < KK * THD; f++) acc = fmaf(sfeat[f], Wout[f * NCLS + tid], acc);
        slog[tid] = acc;
    }
    if (tid < 64) sred[tid] = 0.f;
    __syncthreads();
    if (tid < KK * KK) {
        int k = tid / KK, j = tid % KK;
        float acc = 0.f;
        for (int d = 0; d < D2; d++) acc = fmaf(sctx[k][d], sctx[j][d], acc);
        acc = acc / (snorm[k] * snorm[j]) - ((k == j) ? 1.f : 0.f);
        sred[tid] = acc * acc;
    }
    __syncthreads();
    if (tid == 0) {
        float m = slog[0];
        for (int c = 1; c < NCLS; c++) m = fmaxf(m, slog[c]);
        float s = 0.f, e[NCLS];
        for (int c = 0; c < NCLS; c++) { e[c] = expf(slog[c] - m); s += e[c]; }
        for (int c = 0; c < NCLS; c++) out[b * NCLS + c] = e[c] / s;
        float rs = 0.f;
        for (int i = 0; i < KK * KK; i++) rs += sred[i];
        g_regpart[b] = sqrtf(rs);
    }
}

// ============== K3d: reg = mean_b regpart =================================
__global__ void k_reg(float* __restrict__ out)
{
    __shared__ float sr[BB];
    int tid = threadIdx.x;
    sr[tid] = g_regpart[tid];
    __syncthreads();
    for (int s = 64; s > 0; s >>= 1) { if (tid < s) sr[tid] += sr[tid + s]; __syncthreads(); }
    if (tid == 0) out[BB * NCLS] = sr[0] / (float)BB;
}

// ===========================================================================
extern "C" void kernel_launch(void* const* d_in, const int* in_sizes, int n_in,
                              void* d_out, int out_size)
{
    const float* x      = (const float*)d_in[0];
    const float* Wih_f  = (const float*)d_in[1];
    const float* Whh_f  = (const float*)d_in[2];
    const float* bih_f  = (const float*)d_in[3];
    const float* bhh_f  = (const float*)d_in[4];
    const float* Wih_b  = (const float*)d_in[5];
    const float* Whh_b  = (const float*)d_in[6];
    const float* bih_b  = (const float*)d_in[7];
    const float* bhh_b  = (const float*)d_in[8];
    const float* ac     = (const float*)d_in[9];
    const float* Wattn  = (const float*)d_in[10];
    const float* battn  = (const float*)d_in[11];
    const float* Wtop   = (const float*)d_in[12];
    const float* btop   = (const float*)d_in[13];
    const float* Wout   = (const float*)d_in[14];
    const float* bout   = (const float*)d_in[15];
    float* out = (float*)d_out;

    cudaFuncSetAttribute(k_gemm, cudaFuncAttributeMaxDynamicSharedMemorySize, GEMM_SMEM);
    cudaFuncSetAttribute(k_rec,  cudaFuncAttributeMaxDynamicSharedMemorySize, REC_SMEM);

    k_convA<<<(MM * (KPAD / 2) + 255) / 256, 256>>>(x);
    k_convB<<<(NPAD * (KPAD / 2) + 255) / 256, 256>>>(Wih_f, Wih_b, bih_f, bih_b);
    k_gemm<<<dim3(MM / BM, NPAD / BN), 256, GEMM_SMEM>>>();
    k_rec<<<128, 480, REC_SMEM>>>(Whh_f, bhh_f, Whh_b, bhh_b);
    k_ctxbase<<<KK, 320>>>(ac, Wattn, battn);
    k_context<<<dim3(KK, BB), 320>>>(Wattn);
    k_attn<<<BB, 256>>>(Wtop, btop, Wout, bout, out);
    k_reg<<<1, BB>>>(out);
}